// round 8
// baseline (speedup 1.0000x reference)
#include <cuda_runtime.h>
#include <stdint.h>

// Unpack padded [B, Lmax, H, D] fp32 -> packed [N, H, D], N = sum(lengths).
// Row = H*D = 2048 floats = 512 float4 = 8 KB.
//
// v3: 8 rows per block, all 16 LDG.128 per thread front-batched (MLP_eff=16)
// before the 16 STG.128. 32-bit float4 offsets (total input = 16.7M float4
// < 2^31) keep register pressure down. Streaming .cs hints both directions.
//
// lengths dtype detected on-device (JAX x64-off downcasts int64 -> int32):
// parse as contiguous int32 AND int64-low-words; whichever sums to N wins.

#define ROW_VEC4        512          // float4 per row
#define THREADS         256
#define VEC_PER_THREAD  (ROW_VEC4 / THREADS)   // 2
#define ROWS_PER_BLOCK  8
#define MAX_B           32

__global__ void __launch_bounds__(THREADS) unpack_rows8_kernel(
    const float4* __restrict__ in,        // [B, Lmax, 512] as float4
    const int* __restrict__ lengths_raw,  // [B] raw words
    float4* __restrict__ out,             // [N, 512] as float4
    int B, int Lmax, int N)
{
    const int n0 = blockIdx.x * ROWS_PER_BLOCK;

    // --- dtype detection (B tiny; L1-resident, uniform across threads) ---
    long long sum32 = 0, sum64 = 0;
    #pragma unroll 8
    for (int i = 0; i < B; ++i) {
        sum32 += __ldg(&lengths_raw[i]);
        sum64 += __ldg(&lengths_raw[2 * i]);
    }
    const bool is64 = (sum64 == (long long)N) && (sum32 != (long long)N);

    // --- resolve source offset (in float4 units) for each of 8 rows ---
    int srcOff[ROWS_PER_BLOCK];           // 32-bit: max 8*4096*512 = 16.7M
    #pragma unroll
    for (int r = 0; r < ROWS_PER_BLOCK; ++r) {
        const int n = n0 + r;
        int s = 0, b = 0, t = 0;
        #pragma unroll 8
        for (int i = 0; i < B; ++i) {
            const int len = is64 ? __ldg(&lengths_raw[2 * i]) : __ldg(&lengths_raw[i]);
            if (n >= s && n < s + len) { b = i; t = n - s; }
            s += len;
        }
        srcOff[r] = (b * Lmax + t) * ROW_VEC4;
    }

    const bool full = (n0 + ROWS_PER_BLOCK <= N);
    const int tx = threadIdx.x;

    if (full) {
        // --- phase 1: 16 independent streaming loads, front-batched ---
        float4 v[ROWS_PER_BLOCK * VEC_PER_THREAD];
        #pragma unroll
        for (int r = 0; r < ROWS_PER_BLOCK; ++r)
            #pragma unroll
            for (int j = 0; j < VEC_PER_THREAD; ++j)
                v[r * VEC_PER_THREAD + j] =
                    __ldcs(&in[srcOff[r] + tx + j * THREADS]);

        // --- phase 2: 16 streaming stores ---
        #pragma unroll
        for (int r = 0; r < ROWS_PER_BLOCK; ++r) {
            float4* dst = out + (size_t)(n0 + r) * ROW_VEC4;
            #pragma unroll
            for (int j = 0; j < VEC_PER_THREAD; ++j)
                __stcs(&dst[tx + j * THREADS], v[r * VEC_PER_THREAD + j]);
        }
    } else {
        // tail block: per-row guarded copy
        for (int r = 0; r < ROWS_PER_BLOCK; ++r) {
            if (n0 + r >= N) break;
            float4* dst = out + (size_t)(n0 + r) * ROW_VEC4;
            #pragma unroll
            for (int j = 0; j < VEC_PER_THREAD; ++j)
                __stcs(&dst[tx + j * THREADS],
                       __ldcs(&in[srcOff[r] + tx + j * THREADS]));
        }
    }
}

extern "C" void kernel_launch(void* const* d_in, const int* in_sizes, int n_in,
                              void* d_out, int out_size)
{
    const float4* packed = (const float4*)d_in[0];   // [B, Lmax, H, D] fp32
    const int* lengths_raw = (const int*)d_in[1];    // [B] (int32 or int64 words)

    int B = in_sizes[1];
    if (B > MAX_B) B = MAX_B;
    long long total_in = in_sizes[0];                     // B*Lmax*2048 floats
    int Lmax = (int)(total_in / ((long long)B * 2048));   // 4096

    int N = out_size / 2048;                              // packed rows

    float4* out = (float4*)d_out;

    int grid = (N + ROWS_PER_BLOCK - 1) / ROWS_PER_BLOCK;
    if (grid < 1) grid = 1;
    unpack_rows8_kernel<<<grid, THREADS>>>(packed, lengths_raw, out, B, Lmax, N);
}